// round 2
// baseline (speedup 1.0000x reference)
#include <cuda_runtime.h>
#include <cuda_bf16.h>
#include <cstdint>

// Diagonal linear recurrence with SiLU pre-activation and self-gating.
//   d  = sigmoid(log_d)            [per channel]
//   xa = silu(x)                   [elementwise]
//   h_t = d*(xa_t + h_{t-1}) + b   [scan over T]
//   out_t = h_t * silu(h_t) = h_t^2 * sigmoid(h_t)
//
// Parallel over B*D lanes (one thread per (batch, channel) pair); serial in T.
// MUFU (EX2+RCP per sigmoid, 2 sigmoids/elem) is the predicted per-SMSP
// bottleneck; memory (512MB total) is the chip-level floor.

__device__ __forceinline__ float fast_sigmoid(float x) {
    // 1 / (1 + exp(-x)):  MUFU.EX2 + FFMA + MUFU.RCP
    return __fdividef(1.0f, 1.0f + __expf(-x));
}

__global__ void __launch_bounds__(128, 1)
e54_scan_kernel(const float* __restrict__ x,
                const float* __restrict__ h0,
                const float* __restrict__ log_d,
                const float* __restrict__ bias,
                float* __restrict__ out,
                float* __restrict__ h_final,   // may be nullptr
                int B, int T, int D)
{
    int idx = blockIdx.x * blockDim.x + threadIdx.x;  // lane = b*D + c
    if (idx >= B * D) return;
    int b = idx / D;
    int c = idx - b * D;

    float dc = fast_sigmoid(log_d[c]);
    float bc = bias[c];
    float h  = h0[idx];

    const float* xp = x   + (size_t)b * T * D + c;
    float*       op = out + (size_t)b * T * D + c;

    // Unroll so the independent x-loads and output-gate math pipeline around
    // the serial h chain (FADD+FFMA, ~9 cyc/step).
    #pragma unroll 8
    for (int t = 0; t < T; t++) {
        float xv = xp[(size_t)t * D];
        float xa = xv * fast_sigmoid(xv);          // silu(x)
        h = dc * (xa + h) + bc;                    // diagonal recurrence
        float y = h * h * fast_sigmoid(h);         // h * silu(h)
        op[(size_t)t * D] = y;
    }

    if (h_final) h_final[idx] = h;
}

extern "C" void kernel_launch(void* const* d_in, const int* in_sizes, int n_in,
                              void* d_out, int out_size)
{
    const float* x     = (const float*)d_in[0];
    const float* h0    = (const float*)d_in[1];
    const float* log_d = (const float*)d_in[2];
    const float* bias  = (const float*)d_in[3];
    float* out = (float*)d_out;

    // Derive dims: x=[B,T,D], h0=[B,D], log_d=[D]
    int D  = in_sizes[2];
    int BD = in_sizes[1];
    int B  = BD / D;
    int T  = in_sizes[0] / BD;

    long long main_elems = (long long)B * T * D;
    float* h_final = nullptr;
    if ((long long)out_size >= main_elems + BD) {
        h_final = out + main_elems;   // harness concatenates (output, h_final)
    }

    int threads = 128;
    int blocks  = (BD + threads - 1) / threads;   // 128 blocks -> 1 warp/SMSP
    e54_scan_kernel<<<blocks, threads>>>(x, h0, log_d, bias, out, h_final, B, T, D);
}

// round 3
// speedup vs baseline: 2.2430x; 2.2430x over previous
#include <cuda_runtime.h>
#include <cuda_bf16.h>
#include <cstdint>

// Diagonal linear recurrence with SiLU pre-activation and self-gating.
//   d  = sigmoid(log_d), xa = silu(x)
//   h_t = d*(xa_t + h_{t-1}) + b,  out_t = h_t^2 * sigmoid(h_t)
//
// R2 changes vs R1 (which was memory-LATENCY bound: DRAM=15%, occ=6%):
//  - U=64 load staging: 64 independent LDGs batched per tile -> ~4MB in
//    flight chip-wide, targeting >6 TB/s (Little's law needs ~2.5MB @ 8TB/s).
//  - sigmoid via HW tanh.approx.f32 (1 MUFU) instead of EX2+RCP (2 MUFU),
//    halving MUFU pressure so memory is the only binding resource.

__device__ __forceinline__ float tanh_fast(float x) {
    float y;
    asm("tanh.approx.f32 %0, %1;" : "=f"(y) : "f"(x));
    return y;
}

__device__ __forceinline__ float fast_sigmoid(float x) {
    // sigmoid(x) = 0.5*tanh(0.5x) + 0.5  -> single MUFU.TANH + FMA
    return fmaf(0.5f, tanh_fast(0.5f * x), 0.5f);
}

constexpr int UNROLL = 64;

__global__ void __launch_bounds__(128, 1)
e54_scan_kernel(const float* __restrict__ x,
                const float* __restrict__ h0,
                const float* __restrict__ log_d,
                const float* __restrict__ bias,
                float* __restrict__ out,
                float* __restrict__ h_final,   // may be nullptr
                int B, int T, int D)
{
    int idx = blockIdx.x * blockDim.x + threadIdx.x;  // lane = b*D + c
    if (idx >= B * D) return;
    int b = idx / D;
    int c = idx - b * D;

    float dc = fast_sigmoid(log_d[c]);
    float bc = bias[c];
    float h  = h0[idx];

    const float* xp = x   + (size_t)b * T * D + c;
    float*       op = out + (size_t)b * T * D + c;

    float xv[UNROLL];

    for (int t0 = 0; t0 < T; t0 += UNROLL) {
        // Stage 1: batch all independent loads (maximize MLP; this is the
        // whole point — in-flight bytes hide the ~320ns DRAM latency).
        #pragma unroll
        for (int u = 0; u < UNROLL; u++) {
            xv[u] = xp[(size_t)(t0 + u) * D];
        }
        // Stage 2: silu(x) — independent per element, pipelines freely.
        #pragma unroll
        for (int u = 0; u < UNROLL; u++) {
            xv[u] = xv[u] * fast_sigmoid(xv[u]);
        }
        // Stage 3: serial recurrence + self-gate + store.
        #pragma unroll
        for (int u = 0; u < UNROLL; u++) {
            h = fmaf(dc, xv[u] + h, bc);               // h = d*(xa+h)+b
            float y = h * h * fast_sigmoid(h);         // h * silu(h)
            op[(size_t)(t0 + u) * D] = y;
        }
    }

    if (h_final) h_final[idx] = h;
}

extern "C" void kernel_launch(void* const* d_in, const int* in_sizes, int n_in,
                              void* d_out, int out_size)
{
    const float* x     = (const float*)d_in[0];
    const float* h0    = (const float*)d_in[1];
    const float* log_d = (const float*)d_in[2];
    const float* bias  = (const float*)d_in[3];
    float* out = (float*)d_out;

    int D  = in_sizes[2];
    int BD = in_sizes[1];
    int B  = BD / D;
    int T  = in_sizes[0] / BD;

    long long main_elems = (long long)B * T * D;
    float* h_final = nullptr;
    if ((long long)out_size >= main_elems + BD) {
        h_final = out + main_elems;   // harness concatenates (output, h_final)
    }

    int threads = 128;
    int blocks  = (BD + threads - 1) / threads;
    e54_scan_kernel<<<blocks, threads>>>(x, h0, log_d, bias, out, h_final, B, T, D);
}